// round 1
// baseline (speedup 1.0000x reference)
#include <cuda_runtime.h>

#define B  8
#define L  8192
#define D  768
#define NE 128
#define P  8128
#define NPAIR (B * P)

// ---- device scratch (no allocations allowed) ----
__device__ float g_emb[B * NE * D];       // 3 MB, mean-pooled span embeddings
__device__ float g_norm[B * NE];          // L2 norms
__device__ float g_sim[B * NE * NE];      // full cosine-sim matrices (512 KB)
__device__ float g_rowstats[B * NE * 2];  // per-row (sum, sumsq) partials
__device__ float g_alpha[B];              // 1/(std + 1e-5)

// ------------------------------------------------------------------
// K1: span mean pool + norm.  One block per (b, e).  192 threads,
// each owns 4 consecutive floats of the 768-dim row (float4 path).
// ------------------------------------------------------------------
__global__ void k_emb(const float* __restrict__ x,
                      const int* __restrict__ starts,
                      const int* __restrict__ lengths) {
    int be  = blockIdx.x;                  // 0..1023
    int b   = be >> 7;
    int s   = starts[be];
    int len = lengths[be];
    int tid = threadIdx.x;                 // 0..191

    const float* xp = x + ((size_t)b * L + s) * D;
    float4 acc = make_float4(0.f, 0.f, 0.f, 0.f);
    for (int t = 0; t < len; ++t) {
        float4 v = ((const float4*)(xp + (size_t)t * D))[tid];
        acc.x += v.x; acc.y += v.y; acc.z += v.z; acc.w += v.w;
    }
    float inv = 1.0f / (float)len;
    acc.x *= inv; acc.y *= inv; acc.z *= inv; acc.w *= inv;
    ((float4*)(g_emb + (size_t)be * D))[tid] = acc;

    float nsq = acc.x * acc.x + acc.y * acc.y + acc.z * acc.z + acc.w * acc.w;
    #pragma unroll
    for (int o = 16; o; o >>= 1) nsq += __shfl_xor_sync(0xffffffffu, nsq, o);

    __shared__ float wpart[6];
    if ((tid & 31) == 0) wpart[tid >> 5] = nsq;
    __syncthreads();
    if (tid == 0) {
        float t = 0.f;
        #pragma unroll
        for (int w = 0; w < 6; ++w) t += wpart[w];
        g_norm[be] = sqrtf(t);
    }
}

// ------------------------------------------------------------------
// K2: cosine similarity row.  One block per (b, i) row, 128 threads:
// thread j computes dot(emb_i, emb_j).  emb_i is staged in shared
// (broadcast LDS.128), emb_j streamed via LDG.128 (L2-resident, 3 MB).
// Also emits deterministic per-row (sum, sumsq) for the std pass.
// ------------------------------------------------------------------
__global__ void k_sim() {
    int be  = blockIdx.x;                  // row (b, i)
    int b   = be >> 7;
    int tid = threadIdx.x;                 // j = tid, 0..127

    __shared__ float4 sa[D / 4];           // 192 x float4 = 3 KB
    const float4* ei = (const float4*)(g_emb + (size_t)be * D);
    sa[tid] = ei[tid];
    if (tid < 64) sa[128 + tid] = ei[128 + tid];
    __syncthreads();

    const float4* ej = (const float4*)(g_emb + (size_t)(b * NE + tid) * D);
    float a0 = 0.f, a1 = 0.f, a2 = 0.f, a3 = 0.f;
    #pragma unroll 8
    for (int d = 0; d < D / 4; ++d) {
        float4 a = sa[d];
        float4 v = ej[d];
        a0 = fmaf(a.x, v.x, a0);
        a1 = fmaf(a.y, v.y, a1);
        a2 = fmaf(a.z, v.z, a2);
        a3 = fmaf(a.w, v.w, a3);
    }
    float dot = (a0 + a1) + (a2 + a3);

    float ni  = g_norm[be];
    float nj  = g_norm[b * NE + tid];
    float val = dot / fmaxf(ni * nj, 1e-8f);
    g_sim[(size_t)be * NE + tid] = val;

    // deterministic block reduce of sum / sumsq
    float s = val, q = val * val;
    #pragma unroll
    for (int o = 16; o; o >>= 1) {
        s += __shfl_xor_sync(0xffffffffu, s, o);
        q += __shfl_xor_sync(0xffffffffu, q, o);
    }
    __shared__ float ws[4], wq[4];
    if ((tid & 31) == 0) { ws[tid >> 5] = s; wq[tid >> 5] = q; }
    __syncthreads();
    if (tid == 0) {
        g_rowstats[2 * be]     = (ws[0] + ws[1]) + (ws[2] + ws[3]);
        g_rowstats[2 * be + 1] = (wq[0] + wq[1]) + (wq[2] + wq[3]);
    }
}

// ------------------------------------------------------------------
// K3: per-batch unbiased std -> alpha = 1/(std + 1e-5).
// ------------------------------------------------------------------
__global__ void k_std() {
    int b   = blockIdx.x;                  // 0..7
    int tid = threadIdx.x;                 // 0..127 (one row each)
    float s = g_rowstats[2 * (b * NE + tid)];
    float q = g_rowstats[2 * (b * NE + tid) + 1];
    #pragma unroll
    for (int o = 16; o; o >>= 1) {
        s += __shfl_xor_sync(0xffffffffu, s, o);
        q += __shfl_xor_sync(0xffffffffu, q, o);
    }
    __shared__ float ws[4], wq[4];
    if ((tid & 31) == 0) { ws[tid >> 5] = s; wq[tid >> 5] = q; }
    __syncthreads();
    if (tid == 0) {
        float S = (ws[0] + ws[1]) + (ws[2] + ws[3]);
        float Q = (wq[0] + wq[1]) + (wq[2] + wq[3]);
        const float N = (float)(NE * NE);
        float var = (Q - S * S / N) / (N - 1.0f);
        float sd  = sqrtf(fmaxf(var, 0.0f));
        g_alpha[b] = 1.0f / (sd + 1e-5f);
    }
}

// ------------------------------------------------------------------
// K4: gather i<j pairs, standardize, MLP 1->128(ReLU)->2.
// Weights staged in shared; all per-iteration reads are broadcasts.
// ------------------------------------------------------------------
__global__ void k_cls(const int* __restrict__ hts,
                      const float* __restrict__ thr_p,
                      const float* __restrict__ W1,
                      const float* __restrict__ b1,
                      const float* __restrict__ W2,
                      const float* __restrict__ b2,
                      float* __restrict__ out) {
    __shared__ float sw1[128], sb1[128], sw2[256];
    int tid = threadIdx.x;
    if (tid < 128) { sw1[tid] = W1[tid]; sb1[tid] = b1[tid]; }
    sw2[tid] = W2[tid];
    __syncthreads();

    int p = blockIdx.x * 256 + tid;
    if (p >= NPAIR) return;

    int b = p / P;
    int i = hts[2 * p];
    int j = hts[2 * p + 1];
    float sv = (g_sim[((size_t)(b * NE + i)) * NE + j] - thr_p[0]) * g_alpha[b];

    float l0 = b2[0], l1 = b2[1];
    #pragma unroll 8
    for (int k = 0; k < 128; ++k) {
        float h = fmaxf(fmaf(sv, sw1[k], sb1[k]), 0.0f);
        l0 = fmaf(h, sw2[2 * k],     l0);
        l1 = fmaf(h, sw2[2 * k + 1], l1);
    }
    ((float2*)out)[p] = make_float2(l0, l1);
}

// ------------------------------------------------------------------
extern "C" void kernel_launch(void* const* d_in, const int* in_sizes, int n_in,
                              void* d_out, int out_size) {
    const float* x       = (const float*)d_in[0];
    const int*   starts  = (const int*)  d_in[1];
    const int*   lengths = (const int*)  d_in[2];
    const int*   hts     = (const int*)  d_in[3];
    const float* thr     = (const float*)d_in[4];
    const float* W1      = (const float*)d_in[5];
    const float* b1      = (const float*)d_in[6];
    const float* W2      = (const float*)d_in[7];
    const float* b2      = (const float*)d_in[8];
    float*       out     = (float*)d_out;

    k_emb<<<B * NE, 192>>>(x, starts, lengths);
    k_sim<<<B * NE, 128>>>();
    k_std<<<B, 128>>>();
    k_cls<<<(NPAIR + 255) / 256, 256>>>(hts, thr, W1, b1, W2, b2, out);
}

// round 2
// speedup vs baseline: 2.9783x; 2.9783x over previous
#include <cuda_runtime.h>

#define B  8
#define L  8192
#define D  768
#define NE 128
#define P  8128
#define NPAIR (B * P)

#define KC  32      // k-chunk for sim tiling
#define PAD 34      // smem row stride (floats): 8B-aligned float2 rows, no read conflicts

// ---- device scratch (no allocations allowed) ----
__device__ float g_emb[B * NE * D];   // 3 MB, mean-pooled span embeddings
__device__ float g_norm[B * NE];      // L2 norms
__device__ float g_sim[B * NE * NE];  // cosine-sim matrices (512 KB)
__device__ float g_alpha[B];          // 1/(std + 1e-5)

// ------------------------------------------------------------------
// K1: span mean pool + norm.  One block per (b, e).  192 threads,
// each owns 4 consecutive floats of the 768-dim row.  4-deep MLP.
// ------------------------------------------------------------------
__global__ void k_emb(const float* __restrict__ x,
                      const int* __restrict__ starts,
                      const int* __restrict__ lengths) {
    int be  = blockIdx.x;                  // 0..1023
    int b   = be >> 7;
    int s   = starts[be];
    int len = lengths[be];
    int tid = threadIdx.x;                 // 0..191

    const float* xp = x + ((size_t)b * L + s) * D;
    float4 a0 = make_float4(0.f,0.f,0.f,0.f), a1 = a0, a2 = a0, a3 = a0;
    int t = 0;
    for (; t + 4 <= len; t += 4) {
        float4 v0 = ((const float4*)(xp + (size_t)(t+0) * D))[tid];
        float4 v1 = ((const float4*)(xp + (size_t)(t+1) * D))[tid];
        float4 v2 = ((const float4*)(xp + (size_t)(t+2) * D))[tid];
        float4 v3 = ((const float4*)(xp + (size_t)(t+3) * D))[tid];
        a0.x += v0.x; a0.y += v0.y; a0.z += v0.z; a0.w += v0.w;
        a1.x += v1.x; a1.y += v1.y; a1.z += v1.z; a1.w += v1.w;
        a2.x += v2.x; a2.y += v2.y; a2.z += v2.z; a2.w += v2.w;
        a3.x += v3.x; a3.y += v3.y; a3.z += v3.z; a3.w += v3.w;
    }
    for (; t < len; ++t) {
        float4 v = ((const float4*)(xp + (size_t)t * D))[tid];
        a0.x += v.x; a0.y += v.y; a0.z += v.z; a0.w += v.w;
    }
    float4 acc;
    acc.x = (a0.x + a1.x) + (a2.x + a3.x);
    acc.y = (a0.y + a1.y) + (a2.y + a3.y);
    acc.z = (a0.z + a1.z) + (a2.z + a3.z);
    acc.w = (a0.w + a1.w) + (a2.w + a3.w);
    float inv = 1.0f / (float)len;
    acc.x *= inv; acc.y *= inv; acc.z *= inv; acc.w *= inv;
    ((float4*)(g_emb + (size_t)be * D))[tid] = acc;

    float nsq = acc.x*acc.x + acc.y*acc.y + acc.z*acc.z + acc.w*acc.w;
    #pragma unroll
    for (int o = 16; o; o >>= 1) nsq += __shfl_xor_sync(0xffffffffu, nsq, o);

    __shared__ float wpart[6];
    if ((tid & 31) == 0) wpart[tid >> 5] = nsq;
    __syncthreads();
    if (tid == 0) {
        float tt = 0.f;
        #pragma unroll
        for (int w = 0; w < 6; ++w) tt += wpart[w];
        g_norm[be] = sqrtf(tt);
    }
}

// ------------------------------------------------------------------
// K2: tiled Gram matrix + cosine normalize.
// Grid: 128 blocks = 8 batches x 4x4 tiles of 32x32.  256 threads,
// each computes a 2x2 micro-tile.  Coalesced float4 global loads,
// transpose-on-store into k-major smem (stride 34 -> float2 reads
// are conflict-free; 2-way STS conflicts only, which are cheap).
// ------------------------------------------------------------------
__global__ void k_sim() {
    __shared__ float As[KC][PAD];   // As[k][i_local]
    __shared__ float Bs[KC][PAD];   // Bs[k][j_local]

    int bid = blockIdx.x;           // 0..127
    int b   = bid >> 4;
    int ti  = (bid >> 2) & 3;
    int tj  = bid & 3;
    int tid = threadIdx.x;          // 0..255
    int tx  = tid & 15;             // j pair
    int ty  = tid >> 4;             // i pair

    const float* Ea = g_emb + ((size_t)(b * NE + ti * 32)) * D;
    const float* Eb = g_emb + ((size_t)(b * NE + tj * 32)) * D;

    int lr = tid >> 3;              // load row 0..31
    int lc = (tid & 7) * 4;         // load col 0..28

    float acc00 = 0.f, acc01 = 0.f, acc10 = 0.f, acc11 = 0.f;

    for (int kc = 0; kc < D; kc += KC) {
        float4 av = *(const float4*)(Ea + (size_t)lr * D + kc + lc);
        float4 bv = *(const float4*)(Eb + (size_t)lr * D + kc + lc);
        __syncthreads();
        As[lc+0][lr] = av.x; As[lc+1][lr] = av.y;
        As[lc+2][lr] = av.z; As[lc+3][lr] = av.w;
        Bs[lc+0][lr] = bv.x; Bs[lc+1][lr] = bv.y;
        Bs[lc+2][lr] = bv.z; Bs[lc+3][lr] = bv.w;
        __syncthreads();
        #pragma unroll
        for (int k = 0; k < KC; ++k) {
            float2 a  = *(const float2*)&As[k][ty * 2];
            float2 bb = *(const float2*)&Bs[k][tx * 2];
            acc00 = fmaf(a.x, bb.x, acc00);
            acc01 = fmaf(a.x, bb.y, acc01);
            acc10 = fmaf(a.y, bb.x, acc10);
            acc11 = fmaf(a.y, bb.y, acc11);
        }
    }

    int i = ti * 32 + ty * 2;
    int j = tj * 32 + tx * 2;
    float ni0 = g_norm[b * NE + i],     ni1 = g_norm[b * NE + i + 1];
    float nj0 = g_norm[b * NE + j],     nj1 = g_norm[b * NE + j + 1];
    float* r0 = g_sim + ((size_t)(b * NE + i)) * NE + j;
    float* r1 = r0 + NE;
    ((float2*)r0)[0] = make_float2(acc00 / fmaxf(ni0 * nj0, 1e-8f),
                                   acc01 / fmaxf(ni0 * nj1, 1e-8f));
    ((float2*)r1)[0] = make_float2(acc10 / fmaxf(ni1 * nj0, 1e-8f),
                                   acc11 / fmaxf(ni1 * nj1, 1e-8f));
}

// ------------------------------------------------------------------
// K3: per-batch unbiased std over the 128x128 sim matrix (L2-resident)
// -> alpha = 1/(std + 1e-5).  One block per batch, deterministic tree.
// ------------------------------------------------------------------
__global__ void k_std() {
    int b   = blockIdx.x;               // 0..7
    int tid = threadIdx.x;              // 0..255
    const float4* sp = (const float4*)(g_sim + (size_t)b * NE * NE);

    float s = 0.f, q = 0.f;
    #pragma unroll 4
    for (int t = tid; t < NE * NE / 4; t += 256) {
        float4 v = sp[t];
        s += (v.x + v.y) + (v.z + v.w);
        q += (v.x*v.x + v.y*v.y) + (v.z*v.z + v.w*v.w);
    }
    #pragma unroll
    for (int o = 16; o; o >>= 1) {
        s += __shfl_xor_sync(0xffffffffu, s, o);
        q += __shfl_xor_sync(0xffffffffu, q, o);
    }
    __shared__ float ws[8], wq[8];
    if ((tid & 31) == 0) { ws[tid >> 5] = s; wq[tid >> 5] = q; }
    __syncthreads();
    if (tid == 0) {
        float S = ((ws[0]+ws[1]) + (ws[2]+ws[3])) + ((ws[4]+ws[5]) + (ws[6]+ws[7]));
        float Q = ((wq[0]+wq[1]) + (wq[2]+wq[3])) + ((wq[4]+wq[5]) + (wq[6]+wq[7]));
        const float N = (float)(NE * NE);
        float var = (Q - S * S / N) / (N - 1.0f);
        float sd  = sqrtf(fmaxf(var, 0.0f));
        g_alpha[b] = 1.0f / (sd + 1e-5f);
    }
}

// ------------------------------------------------------------------
// K4: gather i<j pairs, standardize, MLP 1->128(ReLU)->2.
// Weights staged in shared as float4; inner loop: 4 LDS.128 + 16 FMA
// per 4 hidden units.  254*256 threads == 65024 pairs exactly.
// ------------------------------------------------------------------
__global__ void k_cls(const int* __restrict__ hts,
                      const float* __restrict__ thr_p,
                      const float* __restrict__ W1,
                      const float* __restrict__ b1,
                      const float* __restrict__ W2,
                      const float* __restrict__ b2,
                      float* __restrict__ out) {
    __shared__ float4 sw1[32];   // W1[128]
    __shared__ float4 sb1[32];   // b1[128]
    __shared__ float4 sw2[64];   // W2[128][2] row-major
    __shared__ float  sbias[2];

    int tid = threadIdx.x;
    if (tid < 32)                   sw1[tid]      = ((const float4*)W1)[tid];
    else if (tid < 64)              sb1[tid - 32] = ((const float4*)b1)[tid - 32];
    else if (tid < 128)             sw2[tid - 64] = ((const float4*)W2)[tid - 64];
    else if (tid < 130)             sbias[tid - 128] = b2[tid - 128];
    __syncthreads();

    int p = blockIdx.x * 256 + tid;         // 0..65023, exact
    int b = p / P;
    int2 ij = ((const int2*)hts)[p];
    float sv = (g_sim[((size_t)(b * NE + ij.x)) * NE + ij.y] - thr_p[0]) * g_alpha[b];

    float l0 = sbias[0], l1 = sbias[1];
    #pragma unroll 8
    for (int kk = 0; kk < 32; ++kk) {
        float4 w1v = sw1[kk];
        float4 b1v = sb1[kk];
        float4 w2a = sw2[2 * kk];       // pairs (w2[4kk+0][0..1], w2[4kk+1][0..1])
        float4 w2b = sw2[2 * kk + 1];   // pairs (w2[4kk+2][0..1], w2[4kk+3][0..1])
        float h0 = fmaxf(fmaf(sv, w1v.x, b1v.x), 0.0f);
        float h1 = fmaxf(fmaf(sv, w1v.y, b1v.y), 0.0f);
        float h2 = fmaxf(fmaf(sv, w1v.z, b1v.z), 0.0f);
        float h3 = fmaxf(fmaf(sv, w1v.w, b1v.w), 0.0f);
        l0 = fmaf(h0, w2a.x, l0);  l1 = fmaf(h0, w2a.y, l1);
        l0 = fmaf(h1, w2a.z, l0);  l1 = fmaf(h1, w2a.w, l1);
        l0 = fmaf(h2, w2b.x, l0);  l1 = fmaf(h2, w2b.y, l1);
        l0 = fmaf(h3, w2b.z, l0);  l1 = fmaf(h3, w2b.w, l1);
    }
    ((float2*)out)[p] = make_float2(l0, l1);
}

// ------------------------------------------------------------------
extern "C" void kernel_launch(void* const* d_in, const int* in_sizes, int n_in,
                              void* d_out, int out_size) {
    const float* x       = (const float*)d_in[0];
    const int*   starts  = (const int*)  d_in[1];
    const int*   lengths = (const int*)  d_in[2];
    const int*   hts     = (const int*)  d_in[3];
    const float* thr     = (const float*)d_in[4];
    const float* W1      = (const float*)d_in[5];
    const float* b1      = (const float*)d_in[6];
    const float* W2      = (const float*)d_in[7];
    const float* b2      = (const float*)d_in[8];
    float*       out     = (float*)d_out;

    k_emb<<<B * NE, 192>>>(x, starts, lengths);
    k_sim<<<B * 16, 256>>>();
    k_std<<<B, 256>>>();
    k_cls<<<NPAIR / 256, 256>>>(hts, thr, W1, b1, W2, b2, out);
}

// round 3
// speedup vs baseline: 2.9810x; 1.0009x over previous
#include <cuda_runtime.h>

#define B  8
#define L  8192
#define D  768
#define NE 128
#define P  8128
#define NPAIR (B * P)

#define KC  32      // k-chunk for sim tiling
#define PAD 34      // smem row stride (floats)

// ---- device scratch (no allocations allowed) ----
__device__ float  g_emb[B * NE * D];   // 3 MB
__device__ float  g_norm[B * NE];
__device__ float  g_sim[B * NE * NE];  // 512 KB
__device__ float2 g_part[B * 16];      // per-sim-block (sum, sumsq)
__device__ float  g_alpha[B];
__device__ unsigned int g_cnt;         // zero-init; reset by last block each call

// ------------------------------------------------------------------
// K1: span mean pool + norm.  One block per (b, e), 192 threads.
// ------------------------------------------------------------------
__global__ void k_emb(const float* __restrict__ x,
                      const int* __restrict__ starts,
                      const int* __restrict__ lengths) {
    int be  = blockIdx.x;
    int b   = be >> 7;
    int s   = starts[be];
    int len = lengths[be];
    int tid = threadIdx.x;

    const float* xp = x + ((size_t)b * L + s) * D;
    float4 a0 = make_float4(0.f,0.f,0.f,0.f), a1 = a0, a2 = a0, a3 = a0;
    int t = 0;
    for (; t + 4 <= len; t += 4) {
        float4 v0 = ((const float4*)(xp + (size_t)(t+0) * D))[tid];
        float4 v1 = ((const float4*)(xp + (size_t)(t+1) * D))[tid];
        float4 v2 = ((const float4*)(xp + (size_t)(t+2) * D))[tid];
        float4 v3 = ((const float4*)(xp + (size_t)(t+3) * D))[tid];
        a0.x += v0.x; a0.y += v0.y; a0.z += v0.z; a0.w += v0.w;
        a1.x += v1.x; a1.y += v1.y; a1.z += v1.z; a1.w += v1.w;
        a2.x += v2.x; a2.y += v2.y; a2.z += v2.z; a2.w += v2.w;
        a3.x += v3.x; a3.y += v3.y; a3.z += v3.z; a3.w += v3.w;
    }
    for (; t < len; ++t) {
        float4 v = ((const float4*)(xp + (size_t)t * D))[tid];
        a0.x += v.x; a0.y += v.y; a0.z += v.z; a0.w += v.w;
    }
    float4 acc;
    acc.x = (a0.x + a1.x) + (a2.x + a3.x);
    acc.y = (a0.y + a1.y) + (a2.y + a3.y);
    acc.z = (a0.z + a1.z) + (a2.z + a3.z);
    acc.w = (a0.w + a1.w) + (a2.w + a3.w);
    float inv = 1.0f / (float)len;
    acc.x *= inv; acc.y *= inv; acc.z *= inv; acc.w *= inv;
    ((float4*)(g_emb + (size_t)be * D))[tid] = acc;

    float nsq = acc.x*acc.x + acc.y*acc.y + acc.z*acc.z + acc.w*acc.w;
    #pragma unroll
    for (int o = 16; o; o >>= 1) nsq += __shfl_xor_sync(0xffffffffu, nsq, o);

    __shared__ float wpart[6];
    if ((tid & 31) == 0) wpart[tid >> 5] = nsq;
    __syncthreads();
    if (tid == 0) {
        float tt = 0.f;
        #pragma unroll
        for (int w = 0; w < 6; ++w) tt += wpart[w];
        g_norm[be] = sqrtf(tt);
    }
}

// ------------------------------------------------------------------
// K2: tiled Gram + cosine normalize + fused std reduction.
// 128 blocks (8 batches x 4x4 tiles of 32x32), 256 threads, 2x2
// micro-tile.  Each block also reduces (sum, sumsq) of its tile;
// the last block to finish (atomic gate) folds the 16 partials per
// batch in fixed index order -> deterministic alpha.
// ------------------------------------------------------------------
__global__ void k_sim() {
    __shared__ float As[KC][PAD];
    __shared__ float Bs[KC][PAD];

    int bid = blockIdx.x;           // 0..127
    int b   = bid >> 4;
    int ti  = (bid >> 2) & 3;
    int tj  = bid & 3;
    int tid = threadIdx.x;          // 0..255
    int tx  = tid & 15;
    int ty  = tid >> 4;

    const float* Ea = g_emb + ((size_t)(b * NE + ti * 32)) * D;
    const float* Eb = g_emb + ((size_t)(b * NE + tj * 32)) * D;

    int lr = tid >> 3;
    int lc = (tid & 7) * 4;

    float acc00 = 0.f, acc01 = 0.f, acc10 = 0.f, acc11 = 0.f;

    for (int kc = 0; kc < D; kc += KC) {
        float4 av = *(const float4*)(Ea + (size_t)lr * D + kc + lc);
        float4 bv = *(const float4*)(Eb + (size_t)lr * D + kc + lc);
        __syncthreads();
        As[lc+0][lr] = av.x; As[lc+1][lr] = av.y;
        As[lc+2][lr] = av.z; As[lc+3][lr] = av.w;
        Bs[lc+0][lr] = bv.x; Bs[lc+1][lr] = bv.y;
        Bs[lc+2][lr] = bv.z; Bs[lc+3][lr] = bv.w;
        __syncthreads();
        #pragma unroll
        for (int k = 0; k < KC; ++k) {
            float2 a  = *(const float2*)&As[k][ty * 2];
            float2 bb = *(const float2*)&Bs[k][tx * 2];
            acc00 = fmaf(a.x, bb.x, acc00);
            acc01 = fmaf(a.x, bb.y, acc01);
            acc10 = fmaf(a.y, bb.x, acc10);
            acc11 = fmaf(a.y, bb.y, acc11);
        }
    }

    int i = ti * 32 + ty * 2;
    int j = tj * 32 + tx * 2;
    float ni0 = g_norm[b * NE + i],     ni1 = g_norm[b * NE + i + 1];
    float nj0 = g_norm[b * NE + j],     nj1 = g_norm[b * NE + j + 1];
    float v00 = acc00 / fmaxf(ni0 * nj0, 1e-8f);
    float v01 = acc01 / fmaxf(ni0 * nj1, 1e-8f);
    float v10 = acc10 / fmaxf(ni1 * nj0, 1e-8f);
    float v11 = acc11 / fmaxf(ni1 * nj1, 1e-8f);
    float* r0 = g_sim + ((size_t)(b * NE + i)) * NE + j;
    ((float2*)r0)[0]        = make_float2(v00, v01);
    ((float2*)(r0 + NE))[0] = make_float2(v10, v11);

    // ---- fused per-tile (sum, sumsq) reduce ----
    float s = (v00 + v01) + (v10 + v11);
    float q = (v00*v00 + v01*v01) + (v10*v10 + v11*v11);
    #pragma unroll
    for (int o = 16; o; o >>= 1) {
        s += __shfl_xor_sync(0xffffffffu, s, o);
        q += __shfl_xor_sync(0xffffffffu, q, o);
    }
    __shared__ float ws[8], wq[8];
    __shared__ int s_last;
    if ((tid & 31) == 0) { ws[tid >> 5] = s; wq[tid >> 5] = q; }
    __syncthreads();
    if (tid == 0) {
        float S = ((ws[0]+ws[1]) + (ws[2]+ws[3])) + ((ws[4]+ws[5]) + (ws[6]+ws[7]));
        float Q = ((wq[0]+wq[1]) + (wq[2]+wq[3])) + ((wq[4]+wq[5]) + (wq[6]+wq[7]));
        g_part[bid] = make_float2(S, Q);
        __threadfence();
        unsigned int old = atomicAdd(&g_cnt, 1u);
        s_last = (old == 127u);
    }
    __syncthreads();
    if (s_last) {
        __threadfence();
        if (tid < B) {            // one thread per batch, fixed-order sum
            float S = 0.f, Q = 0.f;
            #pragma unroll
            for (int t = 0; t < 16; ++t) {
                float2 pp = g_part[tid * 16 + t];
                S += pp.x; Q += pp.y;
            }
            const float N = (float)(NE * NE);
            float var = (Q - S * S / N) / (N - 1.0f);
            g_alpha[tid] = 1.0f / (sqrtf(fmaxf(var, 0.0f)) + 1e-5f);
        }
        if (tid == 0) g_cnt = 0u;   // reset for next graph replay
    }
}

// ------------------------------------------------------------------
// K3: pairs + MLP.  2 threads per pair; each handles 64 hidden units
// as 4 independent FMA chains, then shfl_xor(1) combine (FP add is
// commutative -> bitwise identical on both lanes).  508 blocks x 256.
// ------------------------------------------------------------------
__global__ void k_cls(const int* __restrict__ hts,
                      const float* __restrict__ thr_p,
                      const float* __restrict__ W1,
                      const float* __restrict__ b1,
                      const float* __restrict__ W2,
                      const float* __restrict__ b2,
                      float* __restrict__ out) {
    __shared__ float4 sw1[32];
    __shared__ float4 sb1[32];
    __shared__ float4 sw2[64];
    __shared__ float  sbias[2];

    int tid = threadIdx.x;
    if (tid < 32)        sw1[tid]       = ((const float4*)W1)[tid];
    else if (tid < 64)   sb1[tid - 32]  = ((const float4*)b1)[tid - 32];
    else if (tid < 128)  sw2[tid - 64]  = ((const float4*)W2)[tid - 64];
    else if (tid < 130)  sbias[tid - 128] = b2[tid - 128];

    int g    = blockIdx.x * 256 + tid;   // 0..130047
    int p    = g >> 1;                   // pair index
    int half = g & 1;
    int b    = p / P;
    int2 ij  = ((const int2*)hts)[p];
    float sv = (g_sim[((size_t)(b * NE + ij.x)) * NE + ij.y] - thr_p[0]) * g_alpha[b];
    __syncthreads();

    int base = half * 16;
    float l0a = 0.f, l1a = 0.f, l0b = 0.f, l1b = 0.f;
    #pragma unroll
    for (int kk = 0; kk < 16; ++kk) {
        int idx = base + kk;
        float4 w1v = sw1[idx];
        float4 b1v = sb1[idx];
        float4 w2a = sw2[2 * idx];
        float4 w2b = sw2[2 * idx + 1];
        float h0 = fmaxf(fmaf(sv, w1v.x, b1v.x), 0.0f);
        float h1 = fmaxf(fmaf(sv, w1v.y, b1v.y), 0.0f);
        float h2 = fmaxf(fmaf(sv, w1v.z, b1v.z), 0.0f);
        float h3 = fmaxf(fmaf(sv, w1v.w, b1v.w), 0.0f);
        l0a = fmaf(h0, w2a.x, l0a);  l1a = fmaf(h0, w2a.y, l1a);
        l0b = fmaf(h1, w2a.z, l0b);  l1b = fmaf(h1, w2a.w, l1b);
        l0a = fmaf(h2, w2b.x, l0a);  l1a = fmaf(h2, w2b.y, l1a);
        l0b = fmaf(h3, w2b.z, l0b);  l1b = fmaf(h3, w2b.w, l1b);
    }
    float l0 = l0a + l0b;
    float l1 = l1a + l1b;
    l0 += __shfl_xor_sync(0xffffffffu, l0, 1);
    l1 += __shfl_xor_sync(0xffffffffu, l1, 1);
    if (half == 0)
        ((float2*)out)[p] = make_float2(l0 + sbias[0], l1 + sbias[1]);
}

// ------------------------------------------------------------------
extern "C" void kernel_launch(void* const* d_in, const int* in_sizes, int n_in,
                              void* d_out, int out_size) {
    const float* x       = (const float*)d_in[0];
    const int*   starts  = (const int*)  d_in[1];
    const int*   lengths = (const int*)  d_in[2];
    const int*   hts     = (const int*)  d_in[3];
    const float* thr     = (const float*)d_in[4];
    const float* W1      = (const float*)d_in[5];
    const float* b1      = (const float*)d_in[6];
    const float* W2      = (const float*)d_in[7];
    const float* b2      = (const float*)d_in[8];
    float*       out     = (float*)d_out;

    k_emb<<<B * NE, 192>>>(x, starts, lengths);
    k_sim<<<B * 16, 256>>>();
    k_cls<<<NPAIR * 2 / 256, 256>>>(hts, thr, W1, b1, W2, b2, out);
}